// round 10
// baseline (speedup 1.0000x reference)
#include <cuda_runtime.h>
#include <math.h>

#define NN   50000
#define FF   64
#define DEG  16
#define HIDN 256
#define NCLS 16
#define NP0  1351
#define NP1  37
#define JP0  1408
#define JP1  40
#define BNEPS 1e-5f

__device__ float d_bnacc[2*FF];
__device__ float d_x0[NN*FF];
__device__ float d_xa[NN*FF];
__device__ float d_xb[NN*FF];
__device__ float d_M0[FF*JP0];
__device__ float d_c0n[JP0];
__device__ float d_M1[FF*JP1];
__device__ float d_c1n[JP1];
__device__ int   d_a0[NN];
__device__ int   d_a1[NP0];
__device__ float d_pool0[NP0*FF];
__device__ float d_cnt0[NP0];
__device__ float d_p1[NP1*FF];
__device__ float d_cnt1[NP1];
__device__ float d_p2[FF];
__device__ float d_corr1[NP0*FF];
__device__ float d_corr2[NP1*FF];
__device__ float d_T0[NP0*FF];
__device__ float d_T1[NP1*FF];
__device__ float d_S4[NN*4];
__device__ float d_wv[NN*DEG];
__device__ unsigned char d_grp[NN*DEG];
__device__ float d_h1[NN*HIDN];
__device__ float d_h2[NN*HIDN];

__device__ __forceinline__ void fma2(unsigned long long &d, unsigned long long a, unsigned long long b) {
    asm("fma.rn.f32x2 %0, %1, %2, %0;" : "+l"(d) : "l"(a), "l"(b));
}
__device__ __forceinline__ unsigned long long dup2(float x) {
    unsigned long long r;
    asm("mov.b64 %0, {%1, %1};" : "=l"(r) : "f"(x));
    return r;
}
__device__ __forceinline__ float2 unpk(unsigned long long v) {
    float2 r;
    asm("mov.b64 {%0, %1}, %2;" : "=f"(r.x), "=f"(r.y) : "l"(v));
    return r;
}
__device__ __forceinline__ unsigned tf32cvt(float x) {
    unsigned r;
    asm("cvt.rna.tf32.f32 %0, %1;" : "=r"(r) : "f"(x));
    return r;
}
__device__ __forceinline__ void mma8(float* d, const unsigned* a, unsigned b0, unsigned b1) {
    asm("mma.sync.aligned.m16n8k8.row.col.f32.tf32.tf32.f32 "
        "{%0,%1,%2,%3},{%4,%5,%6,%7},{%8,%9},{%0,%1,%2,%3};"
        : "+f"(d[0]), "+f"(d[1]), "+f"(d[2]), "+f"(d[3])
        : "r"(a[0]), "r"(a[1]), "r"(a[2]), "r"(a[3]), "r"(b0), "r"(b1));
}

__global__ void zero_kernel() {
    int t = blockIdx.x * blockDim.x + threadIdx.x;
    if (t < 2*FF)   d_bnacc[t] = 0.f;
    if (t < NP0)    d_cnt0[t]  = 0.f;
    if (t < NP1)    d_cnt1[t]  = 0.f;
    if (t < NP0*FF) d_pool0[t] = 0.f;
    if (t < NP1*FF) d_p1[t]    = 0.f;
}

__global__ void bn_stats_kernel(const float* __restrict__ x) {
    __shared__ float ss[4][64], sq[4][64];
    int t = threadIdx.x;
    int f = t & 63, sub = t >> 6;
    float s = 0.f, q = 0.f;
    for (int i = blockIdx.x * 4 + sub; i < NN; i += gridDim.x * 4) {
        float v = x[i*FF + f];
        s += v; q += v*v;
    }
    ss[sub][f] = s; sq[sub][f] = q;
    __syncthreads();
    if (t < 64) {
        atomicAdd(&d_bnacc[t],    ss[0][t]+ss[1][t]+ss[2][t]+ss[3][t]);
        atomicAdd(&d_bnacc[64+t], sq[0][t]+sq[1][t]+sq[2][t]+sq[3][t]);
    }
}

__global__ void bn_apply_kernel(const float* __restrict__ x,
                                const float* __restrict__ gamma,
                                const float* __restrict__ beta) {
    int t = blockIdx.x * blockDim.x + threadIdx.x;
    if (t >= NN*FF) return;
    int f = t & 63;
    float mu  = d_bnacc[f] * (1.f / NN);
    float var = d_bnacc[64+f] * (1.f / NN) - mu * mu;
    float sc  = gamma[f] * rsqrtf(var + BNEPS);
    d_x0[t] = (x[t] - mu) * sc + beta[f];
}

// merged: blocks [0,352) M0, [352,362) M1, [362,538) cn0, [538,543) cn1
#define MB0 352
#define MB1 362
#define CB0 538
#define CB1 543
__global__ void __launch_bounds__(256) prep_kernel(const float* __restrict__ W0c,
                                                   const float* __restrict__ C0c,
                                                   const float* __restrict__ W1c,
                                                   const float* __restrict__ C1c) {
    int b = blockIdx.x;
    int t = threadIdx.x;
    if (b < MB1) {
        int mode = (b >= MB0);
        const float* W = mode ? W1c : W0c;
        const float* C = mode ? C1c : C0c;
        int J  = mode ? NP1 : NP0;
        int JP = mode ? JP1 : JP0;
        float* M = mode ? d_M1 : d_M0;
        __shared__ float Cs[4][HIDN];
        __shared__ float Ws[64][65];
        int f = t & 63, jl = t >> 6;
        int jb = (mode ? (b - MB0) : b) * 4;
        for (int idx = t; idx < 4*HIDN; idx += 256) {
            int jj = idx >> 8, h = idx & 255;
            int j = jb + jj;
            Cs[jj][h] = (j < J) ? C[j*HIDN + h] : 0.f;
        }
        float d0=0.f, d1=0.f, d2=0.f, d3=0.f;
        for (int h0 = 0; h0 < HIDN; h0 += 64) {
            __syncthreads();
            #pragma unroll
            for (int i = 0; i < 16; i++) {
                int idx = t + i*256;
                Ws[idx>>6][idx&63] = W[(idx>>6)*HIDN + h0 + (idx&63)];
            }
            __syncthreads();
            #pragma unroll
            for (int h = 0; h < 64; h += 4) {
                d0 = fmaf(Ws[f][h],   Cs[jl][h0+h],   d0);
                d1 = fmaf(Ws[f][h+1], Cs[jl][h0+h+1], d1);
                d2 = fmaf(Ws[f][h+2], Cs[jl][h0+h+2], d2);
                d3 = fmaf(Ws[f][h+3], Cs[jl][h0+h+3], d3);
            }
        }
        int j = jb + jl;
        if (j < JP) M[f*JP + j] = (j < J) ? (d0+d1)+(d2+d3) : 0.f;
    } else {
        int mode = (b >= CB0);
        const float* C = mode ? C1c : C0c;
        int J  = mode ? NP1 : NP0;
        int JP = mode ? JP1 : JP0;
        float* cn = mode ? d_c1n : d_c0n;
        int bl = mode ? (b - CB0) : (b - MB1);
        int w = bl*8 + (t >> 5);
        int lane = t & 31;
        if (w >= JP) return;
        if (w < J) {
            float s = 0.f;
            for (int h = lane; h < HIDN; h += 32) { float v = C[w*HIDN + h]; s = fmaf(v, v, s); }
            #pragma unroll
            for (int o = 16; o; o >>= 1) s += __shfl_xor_sync(0xffffffffu, s, o);
            if (lane == 0) cn[w] = s;
        } else if (lane == 0) cn[w] = 1e30f;
    }
}

// FFMA2 assign0 with fused pool0 accumulation (xcov tile reused from smem)
__global__ void __launch_bounds__(256) assign0_kernel(const float* __restrict__ xcov) {
    extern __shared__ float sm[];
    float* xs   = sm;                 // [64][128]  (kept intact for pooling)
    float* ms   = sm + 8192;          // [64][128]
    float* redd = sm + 16384;         // [16][128]
    float* cs   = sm + 18432;         // [128] (reused as a0s ints after loop)
    int*   redj = (int*)(sm + 18560); // [16][128]
    int*   a0s  = (int*)cs;
    int t = threadIdx.x;
    int tx = t & 15, ty = t >> 4;
    int base = blockIdx.x * 128;

    #pragma unroll
    for (int q = t; q < 2048; q += 256) {
        int n = q >> 4, fq = q & 15;
        int gi = base + n;
        float4 v = make_float4(0,0,0,0);
        if (gi < NN) v = *(const float4*)&xcov[gi*FF + fq*4];
        xs[(fq*4+0)*128 + n] = v.x;
        xs[(fq*4+1)*128 + n] = v.y;
        xs[(fq*4+2)*128 + n] = v.z;
        xs[(fq*4+3)*128 + n] = v.w;
    }

    float bestd[8]; int bestj[8];
    #pragma unroll
    for (int r = 0; r < 8; r++) { bestd[r] = 1e30f; bestj[r] = 0; }

    for (int jt = 0; jt < JP0; jt += 128) {
        __syncthreads();
        #pragma unroll
        for (int q = t; q < 2048; q += 256) {
            int f = q >> 5, jq = q & 31;
            *(float4*)&ms[f*128 + jq*4] = *(const float4*)&d_M0[f*JP0 + jt + jq*4];
        }
        if (t < 128) cs[t] = d_c0n[jt + t];
        __syncthreads();

        unsigned long long acc[8][4];
        #pragma unroll
        for (int r = 0; r < 8; r++)
            #pragma unroll
            for (int p = 0; p < 4; p++) acc[r][p] = 0ull;

        #pragma unroll 4
        for (int f = 0; f < 64; f++) {
            float4 xl = *(const float4*)&xs[f*128 + ty*8];
            float4 xh = *(const float4*)&xs[f*128 + ty*8 + 4];
            ulonglong2 b01 = *(const ulonglong2*)&ms[f*128 + tx*8];
            ulonglong2 b23 = *(const ulonglong2*)&ms[f*128 + tx*8 + 4];
            float xv[8] = {xl.x, xl.y, xl.z, xl.w, xh.x, xh.y, xh.z, xh.w};
            #pragma unroll
            for (int r = 0; r < 8; r++) {
                unsigned long long a = dup2(xv[r]);
                fma2(acc[r][0], a, b01.x);
                fma2(acc[r][1], a, b01.y);
                fma2(acc[r][2], a, b23.x);
                fma2(acc[r][3], a, b23.y);
            }
        }
        float cv[8];
        #pragma unroll
        for (int u = 0; u < 8; u++) cv[u] = cs[tx*8 + u];
        #pragma unroll
        for (int r = 0; r < 8; r++) {
            #pragma unroll
            for (int p = 0; p < 4; p++) {
                float2 v = unpk(acc[r][p]);
                float q0 = cv[2*p]   - 2.f*v.x;
                float q1 = cv[2*p+1] - 2.f*v.y;
                int jb = jt + tx*8 + 2*p;
                if (q0 < bestd[r]) { bestd[r] = q0; bestj[r] = jb; }
                if (q1 < bestd[r]) { bestd[r] = q1; bestj[r] = jb+1; }
            }
        }
    }

    __syncthreads();
    #pragma unroll
    for (int r = 0; r < 8; r++) {
        int node = ty*8 + r;
        redd[tx*128 + node] = bestd[r];
        redj[tx*128 + node] = bestj[r];
    }
    __syncthreads();
    if (t < 128) {
        float bd = redd[t]; int bj = redj[t];
        #pragma unroll
        for (int g = 1; g < 16; g++) {
            float dv = redd[g*128 + t]; int jv = redj[g*128 + t];
            if (dv < bd || (dv == bd && jv < bj)) { bd = dv; bj = jv; }
        }
        a0s[t] = bj;
        int gi = base + t;
        if (gi < NN) {
            d_a0[gi] = bj;
            atomicAdd(&d_cnt0[bj], 1.f);
        }
    }
    __syncthreads();
    // fused pool0 accumulation: xs[f][n] still holds the xcov tile
    int nvalid = NN - base;
    if (nvalid > 128) nvalid = 128;
    for (int idx = t; idx < 64*128; idx += 256) {
        int n = idx & 127, f = idx >> 7;
        if (n < nvalid) {
            atomicAdd(&d_pool0[a0s[n]*FF + f], xs[f*128 + n]);
        }
    }
}

// pool0 -> p1 accumulation (mode-1 of old pool_accum)
__global__ void pool1_accum_kernel() {
    int t = blockIdx.x * blockDim.x + threadIdx.x;
    if (t >= NP0*FF) return;
    int i = t >> 6, f = t & 63;
    int cl = d_a1[i];
    atomicAdd(&d_p1[cl*FF + f], d_pool0[t]);
    if (f == 0) atomicAdd(&d_cnt1[cl], 1.f);
}

__global__ void assign1_kernel() {
    int i = blockIdx.x * blockDim.x + threadIdx.x;
    if (i >= NP0) return;
    float inv = 1.f / fmaxf(d_cnt0[i], 1.f);
    float xr[FF];
    #pragma unroll
    for (int f = 0; f < FF; f++) {
        float v = d_pool0[i*FF + f] * inv;
        d_pool0[i*FF + f] = v;
        xr[f] = v;
    }
    float best = 1e30f; int bj = 0;
    for (int j = 0; j < NP1; j++) {
        float dot = 0.f;
        #pragma unroll
        for (int f = 0; f < FF; f++) dot = fmaf(xr[f], d_M1[f*JP1 + j], dot);
        float dd = d_c1n[j] - 2.f * dot;
        if (dd < best) { best = dd; bj = j; }
    }
    d_a1[i] = bj;
}

__global__ void level1_kernel(const float* __restrict__ fcorr) {
    int t = threadIdx.x;
    for (int idx = t; idx < NP1*FF; idx += 256)
        d_p1[idx] = d_p1[idx] / fmaxf(d_cnt1[idx >> 6], 1.f);
    __syncthreads();
    if (t < FF) {
        float s = 0.f;
        for (int i = 0; i < NP1; i++) s += d_p1[i*FF + t];
        d_p2[t] = s * (1.f / NP1);
    }
    __syncthreads();
    for (int idx = t; idx < NP1*FF; idx += 256) {
        int f = idx & 63;
        float diff = d_p1[idx] - d_p2[f];
        float c2 = diff * diff;
        d_corr2[idx] = c2;
        float g = 2.f / (1.f + expf(-(fcorr[f] - c2)));
        d_T1[idx] = expf(g * g);
    }
}

__global__ void corr1_kernel() {
    int t = blockIdx.x * blockDim.x + threadIdx.x;
    if (t >= NP0*FF) return;
    int i = t >> 6, f = t & 63;
    int a = d_a1[i];
    float diff = d_pool0[t] - d_p1[a*FF + f];
    float c1 = diff * diff;
    d_corr1[t] = c1;
    float g = 2.f / (1.f + expf(-(d_corr2[a*FF + f] - c1)));
    d_T0[t] = expf(g * g);
}

__global__ void loss_kernel(float* __restrict__ out) {
    __shared__ float sred[256];
    int t = threadIdx.x;
    float s = 0.f;
    for (int idx = t; idx < NP0*FF; idx += 256) s += d_corr1[idx] * (1.f / NP0);
    for (int idx = t; idx < NP1*FF; idx += 256) s += d_corr2[idx] * (1.f / NP1);
    sred[t] = s;
    __syncthreads();
    for (int ofs = 128; ofs > 0; ofs >>= 1) {
        if (t < ofs) sred[t] += sred[t + ofs];
        __syncthreads();
    }
    if (t == 0) out[NN*NCLS] = sred[0] * (1.f / FF) * 0.5f;
}

__global__ void prop0_kernel(const float* __restrict__ av, const int* __restrict__ cols) {
    int wid  = (blockIdx.x * blockDim.x + threadIdx.x) >> 5;
    int lane = threadIdx.x & 31;
    if (wid >= NN) return;
    int i = wid;
    int c_l = 0, g_l = 0; float w_l = 0.f;
    int myc0 = d_a0[i];
    int myc1 = d_a1[myc0];
    if (lane < 16) {
        int e = i*DEG + lane;
        c_l = cols[e];
        w_l = expf(av[e]);
        int cc0 = d_a0[c_l];
        g_l = ((cc0 == myc0) ? 1 : 0) + ((d_a1[cc0] == myc1) ? 2 : 0);
        d_wv[e] = w_l;
        d_grp[e] = (unsigned char)g_l;
    }
    float s0 = (g_l == 0 && lane < 16) ? w_l : 0.f;
    float s1 = (g_l == 1) ? w_l : 0.f;
    float s2 = (g_l == 2) ? w_l : 0.f;
    float s3 = (g_l == 3) ? w_l : 0.f;
    #pragma unroll
    for (int o = 16; o; o >>= 1) {
        s0 += __shfl_xor_sync(0xffffffffu, s0, o);
        s1 += __shfl_xor_sync(0xffffffffu, s1, o);
        s2 += __shfl_xor_sync(0xffffffffu, s2, o);
        s3 += __shfl_xor_sync(0xffffffffu, s3, o);
    }
    if (lane == 0) *(float4*)(d_S4 + i*4) = make_float4(s0, s1, s2, s3);

    float p0a=0,p1a=0,p2a=0,p3a=0, p0b=0,p1b=0,p2b=0,p3b=0;
    #pragma unroll
    for (int e = 0; e < DEG; e++) {
        int   c = __shfl_sync(0xffffffffu, c_l, e);
        float w = __shfl_sync(0xffffffffu, w_l, e);
        int   g = __shfl_sync(0xffffffffu, g_l, e);
        const float* xr = d_x0 + c*FF;
        float va = xr[lane];
        float vb = xr[lane + 32];
        if (g == 0)      { p0a=fmaf(w,va,p0a); p0b=fmaf(w,vb,p0b); }
        else if (g == 1) { p1a=fmaf(w,va,p1a); p1b=fmaf(w,vb,p1b); }
        else if (g == 2) { p2a=fmaf(w,va,p2a); p2b=fmaf(w,vb,p2b); }
        else             { p3a=fmaf(w,va,p3a); p3b=fmaf(w,vb,p3b); }
    }
    float t0a = d_T0[myc0*FF + lane], t0b = d_T0[myc0*FF + 32 + lane];
    float t1a = d_T1[myc1*FF + lane], t1b = d_T1[myc1*FF + 32 + lane];
    float dena = s0 + t0a*s1 + t1a*s2 + t0a*t1a*s3;
    float numa = p0a + t0a*p1a + t1a*p2a + t0a*t1a*p3a;
    float denb = s0 + t0b*s1 + t1b*s2 + t0b*t1b*s3;
    float numb = p0b + t0b*p1b + t1b*p2b + t0b*t1b*p3b;
    int o = i*FF + lane;
    d_xa[o]      = numa/dena + d_x0[o];
    d_xa[o + 32] = numb/denb + d_x0[o + 32];
}

__global__ void prop1_kernel(const int* __restrict__ cols) {
    int wid  = (blockIdx.x * blockDim.x + threadIdx.x) >> 5;
    int lane = threadIdx.x & 31;
    if (wid >= NN) return;
    int i = wid;
    int c_l = 0, g_l = 0; float w_l = 0.f;
    if (lane < 16) {
        int e = i*DEG + lane;
        c_l = cols[e]; g_l = d_grp[e]; w_l = d_wv[e];
    }
    float p0a=0,p1a=0,p2a=0,p3a=0, p0b=0,p1b=0,p2b=0,p3b=0;
    #pragma unroll
    for (int e = 0; e < DEG; e++) {
        int   c = __shfl_sync(0xffffffffu, c_l, e);
        float w = __shfl_sync(0xffffffffu, w_l, e);
        int   g = __shfl_sync(0xffffffffu, g_l, e);
        const float* xr = d_xa + c*FF;
        float va = xr[lane];
        float vb = xr[lane + 32];
        if (g == 0)      { p0a=fmaf(w,va,p0a); p0b=fmaf(w,vb,p0b); }
        else if (g == 1) { p1a=fmaf(w,va,p1a); p1b=fmaf(w,vb,p1b); }
        else if (g == 2) { p2a=fmaf(w,va,p2a); p2b=fmaf(w,vb,p2b); }
        else             { p3a=fmaf(w,va,p3a); p3b=fmaf(w,vb,p3b); }
    }
    int c0 = d_a0[i];
    int c1 = d_a1[c0];
    float4 sv = *(const float4*)(d_S4 + i*4);
    float t0a = d_T0[c0*FF + lane], t0b = d_T0[c0*FF + 32 + lane];
    float t1a = d_T1[c1*FF + lane], t1b = d_T1[c1*FF + 32 + lane];
    float dena = sv.x + t0a*sv.y + t1a*sv.z + t0a*t1a*sv.w;
    float numa = p0a  + t0a*p1a  + t1a*p2a  + t0a*t1a*p3a;
    float denb = sv.x + t0b*sv.y + t1b*sv.z + t0b*t1b*sv.w;
    float numb = p0b  + t0b*p1b  + t1b*p2b  + t0b*t1b*p3b;
    int o = i*FF + lane;
    d_xb[o]      = numa/dena + d_x0[o];
    d_xb[o + 32] = numb/denb + d_x0[o + 32];
}

__global__ void __launch_bounds__(256) gemm_tc_kernel(
        int mode, const float* __restrict__ W, const float* __restrict__ bias,
        const float* __restrict__ ps) {
    const float* A  = mode ? d_h1 : d_xb;
    const float* A2 = mode ? d_h1 : d_x0;
    float* out = mode ? d_h2 : d_h1;
    int splitK = mode ? 256 : 64;
    int K      = mode ? 256 : 128;
    int lda    = mode ? 256 : 64;
    __shared__ unsigned As[128*36];
    __shared__ unsigned Bs[32*136];
    int t = threadIdx.x;
    int lane = t & 31, warp = t >> 5;
    int wm = warp >> 1, wn = warp & 1;
    int grp = lane >> 2, qid = lane & 3;
    int rb = blockIdx.x * 128, cb = blockIdx.y * 128;
    float acc[2][8][4];
    #pragma unroll
    for (int mi = 0; mi < 2; mi++)
        #pragma unroll
        for (int nj = 0; nj < 8; nj++)
            #pragma unroll
            for (int c = 0; c < 4; c++) acc[mi][nj][c] = 0.f;

    int arow = t & 127, ahalf = t >> 7;
    int bk = t >> 5, bcq = t & 31;

    for (int k0 = 0; k0 < K; k0 += 32) {
        #pragma unroll
        for (int i = 0; i < 4; i++) {
            int kq = ahalf + 2*i;
            int kc = k0 + kq*4;
            int row = rb + arow;
            float4 v = make_float4(0,0,0,0);
            if (row < NN) {
                const float* src; int col;
                if (kc < splitK) { src = A;  col = kc; }
                else             { src = A2; col = kc - splitK; }
                v = *(const float4*)&src[row*lda + col];
            }
            As[arow*36 + kq*4 + 0] = tf32cvt(v.x);
            As[arow*36 + kq*4 + 1] = tf32cvt(v.y);
            As[arow*36 + kq*4 + 2] = tf32cvt(v.z);
            As[arow*36 + kq*4 + 3] = tf32cvt(v.w);
        }
        #pragma unroll
        for (int i = 0; i < 4; i++) {
            int k = bk + 8*i;
            float4 v = *(const float4*)&W[(k0+k)*HIDN + cb + bcq*4];
            Bs[k*136 + bcq*4 + 0] = tf32cvt(v.x);
            Bs[k*136 + bcq*4 + 1] = tf32cvt(v.y);
            Bs[k*136 + bcq*4 + 2] = tf32cvt(v.z);
            Bs[k*136 + bcq*4 + 3] = tf32cvt(v.w);
        }
        __syncthreads();
        #pragma unroll
        for (int kk = 0; kk < 4; kk++) {
            int kb = kk*8;
            unsigned a[2][4];
            #pragma unroll
            for (int mi = 0; mi < 2; mi++) {
                int r0 = wm*32 + mi*16 + grp;
                a[mi][0] = As[r0*36 + kb + qid];
                a[mi][1] = As[(r0+8)*36 + kb + qid];
                a[mi][2] = As[r0*36 + kb + 4 + qid];
                a[mi][3] = As[(r0+8)*36 + kb + 4 + qid];
            }
            #pragma unroll
            for (int nj = 0; nj < 8; nj++) {
                int col = wn*64 + nj*8 + grp;
                unsigned b0 = Bs[(kb + qid)*136 + col];
                unsigned b1 = Bs[(kb + 4 + qid)*136 + col];
                mma8(acc[0][nj], a[0], b0, b1);
                mma8(acc[1][nj], a[1], b0, b1);
            }
        }
        __syncthreads();
    }
    float slope = ps[0];
    #pragma unroll
    for (int mi = 0; mi < 2; mi++) {
        int row0 = rb + wm*32 + mi*16 + grp;
        #pragma unroll
        for (int nj = 0; nj < 8; nj++) {
            int col = cb + wn*64 + nj*8 + qid*2;
            float2 bq = *(const float2*)&bias[col];
            float v0 = acc[mi][nj][0] + bq.x;
            float v1 = acc[mi][nj][1] + bq.y;
            float v2 = acc[mi][nj][2] + bq.x;
            float v3 = acc[mi][nj][3] + bq.y;
            v0 = (v0 >= 0.f) ? v0 : slope*v0;
            v1 = (v1 >= 0.f) ? v1 : slope*v1;
            v2 = (v2 >= 0.f) ? v2 : slope*v2;
            v3 = (v3 >= 0.f) ? v3 : slope*v3;
            if (row0 < NN)     *(float2*)&out[row0*HIDN + col]     = make_float2(v0, v1);
            if (row0 + 8 < NN) *(float2*)&out[(row0+8)*HIDN + col] = make_float2(v2, v3);
        }
    }
}

#define HPITCH 260
__global__ void __launch_bounds__(256) head_kernel(const float* __restrict__ W3,
                                                   const float* __restrict__ b3,
                                                   float* __restrict__ out) {
    extern __shared__ float hs[];
    float* ls = hs + 64*HPITCH;
    __shared__ float w3s[HIDN*NCLS];
    int t = threadIdx.x;
    for (int idx = t; idx < HIDN*NCLS; idx += 256) w3s[idx] = W3[idx];
    int base = blockIdx.x * 64;
    for (int idx = t; idx < 64*64; idx += 256) {
        int r = idx >> 6, c4 = idx & 63;
        int gi = base + r;
        float4 v = make_float4(0,0,0,0);
        if (gi < NN) v = *(const float4*)&d_h2[gi*HIDN + c4*4];
        *(float4*)&hs[r*HPITCH + c4*4] = v;
    }
    __syncthreads();
    int r = t >> 2, q = t & 3;
    float4 a = *(const float4*)&b3[q*4];
    const float* hrow = hs + r*HPITCH;
    #pragma unroll 8
    for (int k = 0; k < HIDN; k++) {
        float h = hrow[k];
        float4 w = *(const float4*)&w3s[k*16 + q*4];
        a.x = fmaf(h, w.x, a.x); a.y = fmaf(h, w.y, a.y);
        a.z = fmaf(h, w.z, a.z); a.w = fmaf(h, w.w, a.w);
    }
    *(float4*)&ls[r*16 + q*4] = a;
    __syncthreads();
    if (t < 64) {
        int gi = base + t;
        if (gi < NN) {
            float v[16];
            #pragma unroll
            for (int c = 0; c < 16; c++) v[c] = ls[t*16 + c];
            float m = v[0];
            #pragma unroll
            for (int c = 1; c < 16; c++) m = fmaxf(m, v[c]);
            float s = 0.f;
            #pragma unroll
            for (int c = 0; c < 16; c++) s += expf(v[c] - m);
            float lse = m + logf(s);
            float* orow = out + gi*NCLS;
            #pragma unroll
            for (int c = 0; c < 16; c += 4) {
                float4 o4 = make_float4(v[c]-lse, v[c+1]-lse, v[c+2]-lse, v[c+3]-lse);
                *(float4*)&orow[c] = o4;
            }
        }
    }
}

extern "C" void kernel_launch(void* const* d_in, const int* in_sizes, int n_in,
                              void* d_out, int out_size) {
    const float* x     = (const float*)d_in[0];
    const float* xcov  = (const float*)d_in[1];
    const float* adjv  = (const float*)d_in[2];
    const float* fcorr = (const float*)d_in[3];
    const float* gamma = (const float*)d_in[4];
    const float* beta  = (const float*)d_in[5];
    const float* W0    = (const float*)d_in[6];
    const float* C0    = (const float*)d_in[7];
    const float* W1    = (const float*)d_in[8];
    const float* C1    = (const float*)d_in[9];
    const float* mW1   = (const float*)d_in[12];
    const float* mb1   = (const float*)d_in[13];
    const float* mp1   = (const float*)d_in[14];
    const float* mW2   = (const float*)d_in[15];
    const float* mb2   = (const float*)d_in[16];
    const float* mp2   = (const float*)d_in[17];
    const float* mW3   = (const float*)d_in[18];
    const float* mb3   = (const float*)d_in[19];
    const int*   cols  = (const int*)d_in[21];
    float* out = (float*)d_out;

    static int inited = 0;
    const int ASMEM = 82432 + 256;
    const int HSMEM = (64*HPITCH + 64*16) * 4;
    if (!inited) {
        cudaFuncSetAttribute(assign0_kernel, cudaFuncAttributeMaxDynamicSharedMemorySize, ASMEM);
        cudaFuncSetAttribute(head_kernel,    cudaFuncAttributeMaxDynamicSharedMemorySize, HSMEM);
        inited = 1;
    }

    zero_kernel<<<338, 256>>>();
    bn_stats_kernel<<<240, 256>>>(x);
    bn_apply_kernel<<<(NN*FF+255)/256, 256>>>(x, gamma, beta);
    prep_kernel<<<CB1, 256>>>(W0, C0, W1, C1);
    assign0_kernel<<<(NN+127)/128, 256, ASMEM>>>(xcov);
    assign1_kernel<<<(NP0+127)/128, 128>>>();
    pool1_accum_kernel<<<(NP0*FF+255)/256, 256>>>();
    level1_kernel<<<1, 256>>>(fcorr);
    corr1_kernel<<<(NP0*FF+255)/256, 256>>>();
    loss_kernel<<<1, 256>>>(out);
    prop0_kernel<<<(NN*32+255)/256, 256>>>(adjv, cols);
    prop1_kernel<<<(NN*32+255)/256, 256>>>(cols);
    dim3 ggrid((NN+127)/128, 2);
    gemm_tc_kernel<<<ggrid, 256>>>(0, mW1, mb1, mp1);
    gemm_tc_kernel<<<ggrid, 256>>>(1, mW2, mb2, mp2);
    head_kernel<<<(NN+63)/64, 256, HSMEM>>>(mW3, mb3, out);
}

// round 11
// speedup vs baseline: 1.8704x; 1.8704x over previous
#include <cuda_runtime.h>
#include <math.h>

#define NN   50000
#define FF   64
#define DEG  16
#define HIDN 256
#define NCLS 16
#define NP0  1351
#define NP1  37
#define JP0  1408
#define JP1  40
#define BNEPS 1e-5f

__device__ float d_bnacc[2*FF];
__device__ float d_x0[NN*FF];
__device__ float d_xa[NN*FF];
__device__ float d_xb[NN*FF];
__device__ float d_M0[FF*JP0];
__device__ float d_c0n[JP0];
__device__ float d_M1[FF*JP1];
__device__ float d_c1n[JP1];
__device__ int   d_a0[NN];
__device__ int   d_a1[NP0];
__device__ float d_pool0[NP0*FF];
__device__ float d_cnt0[NP0];
__device__ float d_p1[NP1*FF];
__device__ float d_cnt1[NP1];
__device__ float d_p2[FF];
__device__ float d_corr1[NP0*FF];
__device__ float d_corr2[NP1*FF];
__device__ float d_T0[NP0*FF];
__device__ float d_T1[NP1*FF];
__device__ float d_S4[NN*4];
__device__ float d_wv[NN*DEG];
__device__ unsigned char d_grp[NN*DEG];
__device__ float d_h1[NN*HIDN];
__device__ float d_h2[NN*HIDN];

__device__ __forceinline__ void fma2(unsigned long long &d, unsigned long long a, unsigned long long b) {
    asm("fma.rn.f32x2 %0, %1, %2, %0;" : "+l"(d) : "l"(a), "l"(b));
}
__device__ __forceinline__ unsigned long long dup2(float x) {
    unsigned long long r;
    asm("mov.b64 %0, {%1, %1};" : "=l"(r) : "f"(x));
    return r;
}
__device__ __forceinline__ float2 unpk(unsigned long long v) {
    float2 r;
    asm("mov.b64 {%0, %1}, %2;" : "=f"(r.x), "=f"(r.y) : "l"(v));
    return r;
}
__device__ __forceinline__ unsigned tf32cvt(float x) {
    unsigned r;
    asm("cvt.rna.tf32.f32 %0, %1;" : "=r"(r) : "f"(x));
    return r;
}
__device__ __forceinline__ void mma8(float* d, const unsigned* a, unsigned b0, unsigned b1) {
    asm("mma.sync.aligned.m16n8k8.row.col.f32.tf32.tf32.f32 "
        "{%0,%1,%2,%3},{%4,%5,%6,%7},{%8,%9},{%0,%1,%2,%3};"
        : "+f"(d[0]), "+f"(d[1]), "+f"(d[2]), "+f"(d[3])
        : "r"(a[0]), "r"(a[1]), "r"(a[2]), "r"(a[3]), "r"(b0), "r"(b1));
}

__global__ void zero_kernel() {
    int t = blockIdx.x * blockDim.x + threadIdx.x;
    if (t < 2*FF)   d_bnacc[t] = 0.f;
    if (t < NP0)    d_cnt0[t]  = 0.f;
    if (t < NP1)    d_cnt1[t]  = 0.f;
    if (t < NP0*FF) d_pool0[t] = 0.f;
    if (t < NP1*FF) d_p1[t]    = 0.f;
}

__global__ void bn_stats_kernel(const float* __restrict__ x) {
    __shared__ float ss[4][64], sq[4][64];
    int t = threadIdx.x;
    int f = t & 63, sub = t >> 6;
    float s = 0.f, q = 0.f;
    for (int i = blockIdx.x * 4 + sub; i < NN; i += gridDim.x * 4) {
        float v = x[i*FF + f];
        s += v; q += v*v;
    }
    ss[sub][f] = s; sq[sub][f] = q;
    __syncthreads();
    if (t < 64) {
        atomicAdd(&d_bnacc[t],    ss[0][t]+ss[1][t]+ss[2][t]+ss[3][t]);
        atomicAdd(&d_bnacc[64+t], sq[0][t]+sq[1][t]+sq[2][t]+sq[3][t]);
    }
}

__global__ void bn_apply_kernel(const float* __restrict__ x,
                                const float* __restrict__ gamma,
                                const float* __restrict__ beta) {
    int t = blockIdx.x * blockDim.x + threadIdx.x;
    if (t >= NN*FF) return;
    int f = t & 63;
    float mu  = d_bnacc[f] * (1.f / NN);
    float var = d_bnacc[64+f] * (1.f / NN) - mu * mu;
    float sc  = gamma[f] * rsqrtf(var + BNEPS);
    d_x0[t] = (x[t] - mu) * sc + beta[f];
}

// merged: blocks [0,352) M0, [352,362) M1, [362,538) cn0, [538,543) cn1
#define MB0 352
#define MB1 362
#define CB0 538
#define CB1 543
__global__ void __launch_bounds__(256) prep_kernel(const float* __restrict__ W0c,
                                                   const float* __restrict__ C0c,
                                                   const float* __restrict__ W1c,
                                                   const float* __restrict__ C1c) {
    int b = blockIdx.x;
    int t = threadIdx.x;
    if (b < MB1) {
        int mode = (b >= MB0);
        const float* W = mode ? W1c : W0c;
        const float* C = mode ? C1c : C0c;
        int J  = mode ? NP1 : NP0;
        int JP = mode ? JP1 : JP0;
        float* M = mode ? d_M1 : d_M0;
        __shared__ float Cs[4][HIDN];
        __shared__ float Ws[64][65];
        int f = t & 63, jl = t >> 6;
        int jb = (mode ? (b - MB0) : b) * 4;
        for (int idx = t; idx < 4*HIDN; idx += 256) {
            int jj = idx >> 8, h = idx & 255;
            int j = jb + jj;
            Cs[jj][h] = (j < J) ? C[j*HIDN + h] : 0.f;
        }
        float d0=0.f, d1=0.f, d2=0.f, d3=0.f;
        for (int h0 = 0; h0 < HIDN; h0 += 64) {
            __syncthreads();
            #pragma unroll
            for (int i = 0; i < 16; i++) {
                int idx = t + i*256;
                Ws[idx>>6][idx&63] = W[(idx>>6)*HIDN + h0 + (idx&63)];
            }
            __syncthreads();
            #pragma unroll
            for (int h = 0; h < 64; h += 4) {
                d0 = fmaf(Ws[f][h],   Cs[jl][h0+h],   d0);
                d1 = fmaf(Ws[f][h+1], Cs[jl][h0+h+1], d1);
                d2 = fmaf(Ws[f][h+2], Cs[jl][h0+h+2], d2);
                d3 = fmaf(Ws[f][h+3], Cs[jl][h0+h+3], d3);
            }
        }
        int j = jb + jl;
        if (j < JP) M[f*JP + j] = (j < J) ? (d0+d1)+(d2+d3) : 0.f;
    } else {
        int mode = (b >= CB0);
        const float* C = mode ? C1c : C0c;
        int J  = mode ? NP1 : NP0;
        int JP = mode ? JP1 : JP0;
        float* cn = mode ? d_c1n : d_c0n;
        int bl = mode ? (b - CB0) : (b - MB1);
        int w = bl*8 + (t >> 5);
        int lane = t & 31;
        if (w >= JP) return;
        if (w < J) {
            float s = 0.f;
            for (int h = lane; h < HIDN; h += 32) { float v = C[w*HIDN + h]; s = fmaf(v, v, s); }
            #pragma unroll
            for (int o = 16; o; o >>= 1) s += __shfl_xor_sync(0xffffffffu, s, o);
            if (lane == 0) cn[w] = s;
        } else if (lane == 0) cn[w] = 1e30f;
    }
}

// pure FFMA2 assign0 (round-8 known good; no fused pooling)
__global__ void __launch_bounds__(256) assign0_kernel(const float* __restrict__ xcov) {
    extern __shared__ float sm[];
    float* xs   = sm;
    float* ms   = sm + 8192;
    float* redd = sm + 16384;
    float* cs   = sm + 18432;
    int*   redj = (int*)(sm + 18560);
    int t = threadIdx.x;
    int tx = t & 15, ty = t >> 4;
    int base = blockIdx.x * 128;

    #pragma unroll
    for (int q = t; q < 2048; q += 256) {
        int n = q >> 4, fq = q & 15;
        int gi = base + n;
        float4 v = make_float4(0,0,0,0);
        if (gi < NN) v = *(const float4*)&xcov[gi*FF + fq*4];
        xs[(fq*4+0)*128 + n] = v.x;
        xs[(fq*4+1)*128 + n] = v.y;
        xs[(fq*4+2)*128 + n] = v.z;
        xs[(fq*4+3)*128 + n] = v.w;
    }

    float bestd[8]; int bestj[8];
    #pragma unroll
    for (int r = 0; r < 8; r++) { bestd[r] = 1e30f; bestj[r] = 0; }

    for (int jt = 0; jt < JP0; jt += 128) {
        __syncthreads();
        #pragma unroll
        for (int q = t; q < 2048; q += 256) {
            int f = q >> 5, jq = q & 31;
            *(float4*)&ms[f*128 + jq*4] = *(const float4*)&d_M0[f*JP0 + jt + jq*4];
        }
        if (t < 128) cs[t] = d_c0n[jt + t];
        __syncthreads();

        unsigned long long acc[8][4];
        #pragma unroll
        for (int r = 0; r < 8; r++)
            #pragma unroll
            for (int p = 0; p < 4; p++) acc[r][p] = 0ull;

        #pragma unroll 4
        for (int f = 0; f < 64; f++) {
            float4 xl = *(const float4*)&xs[f*128 + ty*8];
            float4 xh = *(const float4*)&xs[f*128 + ty*8 + 4];
            ulonglong2 b01 = *(const ulonglong2*)&ms[f*128 + tx*8];
            ulonglong2 b23 = *(const ulonglong2*)&ms[f*128 + tx*8 + 4];
            float xv[8] = {xl.x, xl.y, xl.z, xl.w, xh.x, xh.y, xh.z, xh.w};
            #pragma unroll
            for (int r = 0; r < 8; r++) {
                unsigned long long a = dup2(xv[r]);
                fma2(acc[r][0], a, b01.x);
                fma2(acc[r][1], a, b01.y);
                fma2(acc[r][2], a, b23.x);
                fma2(acc[r][3], a, b23.y);
            }
        }
        float cv[8];
        #pragma unroll
        for (int u = 0; u < 8; u++) cv[u] = cs[tx*8 + u];
        #pragma unroll
        for (int r = 0; r < 8; r++) {
            #pragma unroll
            for (int p = 0; p < 4; p++) {
                float2 v = unpk(acc[r][p]);
                float q0 = cv[2*p]   - 2.f*v.x;
                float q1 = cv[2*p+1] - 2.f*v.y;
                int jb = jt + tx*8 + 2*p;
                if (q0 < bestd[r]) { bestd[r] = q0; bestj[r] = jb; }
                if (q1 < bestd[r]) { bestd[r] = q1; bestj[r] = jb+1; }
            }
        }
    }

    __syncthreads();
    #pragma unroll
    for (int r = 0; r < 8; r++) {
        int node = ty*8 + r;
        redd[tx*128 + node] = bestd[r];
        redj[tx*128 + node] = bestj[r];
    }
    __syncthreads();
    if (t < 128) {
        float bd = redd[t]; int bj = redj[t];
        #pragma unroll
        for (int g = 1; g < 16; g++) {
            float dv = redd[g*128 + t]; int jv = redj[g*128 + t];
            if (dv < bd || (dv == bd && jv < bj)) { bd = dv; bj = jv; }
        }
        int gi = base + t;
        if (gi < NN) d_a0[gi] = bj;
    }
}

// coalesced pooling: warp covers consecutive f of one node -> contiguous atomics
__global__ void pool0_accum_kernel(const float* __restrict__ xcov) {
    int t = blockIdx.x * blockDim.x + threadIdx.x;
    if (t >= NN*FF) return;
    int i = t >> 6, f = t & 63;
    int cl = d_a0[i];
    atomicAdd(&d_pool0[cl*FF + f], xcov[t]);
    if (f == 0) atomicAdd(&d_cnt0[cl], 1.f);
}

__global__ void pool1_accum_kernel() {
    int t = blockIdx.x * blockDim.x + threadIdx.x;
    if (t >= NP0*FF) return;
    int i = t >> 6, f = t & 63;
    int cl = d_a1[i];
    atomicAdd(&d_p1[cl*FF + f], d_pool0[t]);
    if (f == 0) atomicAdd(&d_cnt1[cl], 1.f);
}

// finalize pool0 (writeback) + assign to level-1 centroids
__global__ void assign1_kernel() {
    int i = blockIdx.x * blockDim.x + threadIdx.x;
    if (i >= NP0) return;
    float inv = 1.f / fmaxf(d_cnt0[i], 1.f);
    float xr[FF];
    #pragma unroll
    for (int f = 0; f < FF; f++) {
        float v = d_pool0[i*FF + f] * inv;
        d_pool0[i*FF + f] = v;
        xr[f] = v;
    }
    float best = 1e30f; int bj = 0;
    for (int j = 0; j < NP1; j++) {
        float dot = 0.f;
        #pragma unroll
        for (int f = 0; f < FF; f++) dot = fmaf(xr[f], d_M1[f*JP1 + j], dot);
        float dd = d_c1n[j] - 2.f * dot;
        if (dd < best) { best = dd; bj = j; }
    }
    d_a1[i] = bj;
}

__global__ void level1_kernel(const float* __restrict__ fcorr) {
    int t = threadIdx.x;
    for (int idx = t; idx < NP1*FF; idx += 256)
        d_p1[idx] = d_p1[idx] / fmaxf(d_cnt1[idx >> 6], 1.f);
    __syncthreads();
    if (t < FF) {
        float s = 0.f;
        for (int i = 0; i < NP1; i++) s += d_p1[i*FF + t];
        d_p2[t] = s * (1.f / NP1);
    }
    __syncthreads();
    for (int idx = t; idx < NP1*FF; idx += 256) {
        int f = idx & 63;
        float diff = d_p1[idx] - d_p2[f];
        float c2 = diff * diff;
        d_corr2[idx] = c2;
        float g = 2.f / (1.f + expf(-(fcorr[f] - c2)));
        d_T1[idx] = expf(g * g);
    }
}

__global__ void corr1_kernel() {
    int t = blockIdx.x * blockDim.x + threadIdx.x;
    if (t >= NP0*FF) return;
    int i = t >> 6, f = t & 63;
    int a = d_a1[i];
    float diff = d_pool0[t] - d_p1[a*FF + f];
    float c1 = diff * diff;
    d_corr1[t] = c1;
    float g = 2.f / (1.f + expf(-(d_corr2[a*FF + f] - c1)));
    d_T0[t] = expf(g * g);
}

__global__ void loss_kernel(float* __restrict__ out) {
    __shared__ float sred[256];
    int t = threadIdx.x;
    float s = 0.f;
    for (int idx = t; idx < NP0*FF; idx += 256) s += d_corr1[idx] * (1.f / NP0);
    for (int idx = t; idx < NP1*FF; idx += 256) s += d_corr2[idx] * (1.f / NP1);
    sred[t] = s;
    __syncthreads();
    for (int ofs = 128; ofs > 0; ofs >>= 1) {
        if (t < ofs) sred[t] += sred[t + ofs];
        __syncthreads();
    }
    if (t == 0) out[NN*NCLS] = sred[0] * (1.f / FF) * 0.5f;
}

__global__ void prop0_kernel(const float* __restrict__ av, const int* __restrict__ cols) {
    int wid  = (blockIdx.x * blockDim.x + threadIdx.x) >> 5;
    int lane = threadIdx.x & 31;
    if (wid >= NN) return;
    int i = wid;
    int c_l = 0, g_l = 0; float w_l = 0.f;
    int myc0 = d_a0[i];
    int myc1 = d_a1[myc0];
    if (lane < 16) {
        int e = i*DEG + lane;
        c_l = cols[e];
        w_l = expf(av[e]);
        int cc0 = d_a0[c_l];
        g_l = ((cc0 == myc0) ? 1 : 0) + ((d_a1[cc0] == myc1) ? 2 : 0);
        d_wv[e] = w_l;
        d_grp[e] = (unsigned char)g_l;
    }
    float s0 = (g_l == 0 && lane < 16) ? w_l : 0.f;
    float s1 = (g_l == 1) ? w_l : 0.f;
    float s2 = (g_l == 2) ? w_l : 0.f;
    float s3 = (g_l == 3) ? w_l : 0.f;
    #pragma unroll
    for (int o = 16; o; o >>= 1) {
        s0 += __shfl_xor_sync(0xffffffffu, s0, o);
        s1 += __shfl_xor_sync(0xffffffffu, s1, o);
        s2 += __shfl_xor_sync(0xffffffffu, s2, o);
        s3 += __shfl_xor_sync(0xffffffffu, s3, o);
    }
    if (lane == 0) *(float4*)(d_S4 + i*4) = make_float4(s0, s1, s2, s3);

    float p0a=0,p1a=0,p2a=0,p3a=0, p0b=0,p1b=0,p2b=0,p3b=0;
    #pragma unroll
    for (int e = 0; e < DEG; e++) {
        int   c = __shfl_sync(0xffffffffu, c_l, e);
        float w = __shfl_sync(0xffffffffu, w_l, e);
        int   g = __shfl_sync(0xffffffffu, g_l, e);
        const float* xr = d_x0 + c*FF;
        float va = xr[lane];
        float vb = xr[lane + 32];
        if (g == 0)      { p0a=fmaf(w,va,p0a); p0b=fmaf(w,vb,p0b); }
        else if (g == 1) { p1a=fmaf(w,va,p1a); p1b=fmaf(w,vb,p1b); }
        else if (g == 2) { p2a=fmaf(w,va,p2a); p2b=fmaf(w,vb,p2b); }
        else             { p3a=fmaf(w,va,p3a); p3b=fmaf(w,vb,p3b); }
    }
    float t0a = d_T0[myc0*FF + lane], t0b = d_T0[myc0*FF + 32 + lane];
    float t1a = d_T1[myc1*FF + lane], t1b = d_T1[myc1*FF + 32 + lane];
    float dena = s0 + t0a*s1 + t1a*s2 + t0a*t1a*s3;
    float numa = p0a + t0a*p1a + t1a*p2a + t0a*t1a*p3a;
    float denb = s0 + t0b*s1 + t1b*s2 + t0b*t1b*s3;
    float numb = p0b + t0b*p1b + t1b*p2b + t0b*t1b*p3b;
    int o = i*FF + lane;
    d_xa[o]      = numa/dena + d_x0[o];
    d_xa[o + 32] = numb/denb + d_x0[o + 32];
}

__global__ void prop1_kernel(const int* __restrict__ cols) {
    int wid  = (blockIdx.x * blockDim.x + threadIdx.x) >> 5;
    int lane = threadIdx.x & 31;
    if (wid >= NN) return;
    int i = wid;
    int c_l = 0, g_l = 0; float w_l = 0.f;
    if (lane < 16) {
        int e = i*DEG + lane;
        c_l = cols[e]; g_l = d_grp[e]; w_l = d_wv[e];
    }
    float p0a=0,p1a=0,p2a=0,p3a=0, p0b=0,p1b=0,p2b=0,p3b=0;
    #pragma unroll
    for (int e = 0; e < DEG; e++) {
        int   c = __shfl_sync(0xffffffffu, c_l, e);
        float w = __shfl_sync(0xffffffffu, w_l, e);
        int   g = __shfl_sync(0xffffffffu, g_l, e);
        const float* xr = d_xa + c*FF;
        float va = xr[lane];
        float vb = xr[lane + 32];
        if (g == 0)      { p0a=fmaf(w,va,p0a); p0b=fmaf(w,vb,p0b); }
        else if (g == 1) { p1a=fmaf(w,va,p1a); p1b=fmaf(w,vb,p1b); }
        else if (g == 2) { p2a=fmaf(w,va,p2a); p2b=fmaf(w,vb,p2b); }
        else             { p3a=fmaf(w,va,p3a); p3b=fmaf(w,vb,p3b); }
    }
    int c0 = d_a0[i];
    int c1 = d_a1[c0];
    float4 sv = *(const float4*)(d_S4 + i*4);
    float t0a = d_T0[c0*FF + lane], t0b = d_T0[c0*FF + 32 + lane];
    float t1a = d_T1[c1*FF + lane], t1b = d_T1[c1*FF + 32 + lane];
    float dena = sv.x + t0a*sv.y + t1a*sv.z + t0a*t1a*sv.w;
    float numa = p0a  + t0a*p1a  + t1a*p2a  + t0a*t1a*p3a;
    float denb = sv.x + t0b*sv.y + t1b*sv.z + t0b*t1b*sv.w;
    float numb = p0b  + t0b*p1b  + t1b*p2b  + t0b*t1b*p3b;
    int o = i*FF + lane;
    d_xb[o]      = numa/dena + d_x0[o];
    d_xb[o + 32] = numb/denb + d_x0[o + 32];
}

__global__ void __launch_bounds__(256) gemm_tc_kernel(
        int mode, const float* __restrict__ W, const float* __restrict__ bias,
        const float* __restrict__ ps) {
    const float* A  = mode ? d_h1 : d_xb;
    const float* A2 = mode ? d_h1 : d_x0;
    float* out = mode ? d_h2 : d_h1;
    int splitK = mode ? 256 : 64;
    int K      = mode ? 256 : 128;
    int lda    = mode ? 256 : 64;
    __shared__ unsigned As[128*36];
    __shared__ unsigned Bs[32*136];
    int t = threadIdx.x;
    int lane = t & 31, warp = t >> 5;
    int wm = warp >> 1, wn = warp & 1;
    int grp = lane >> 2, qid = lane & 3;
    int rb = blockIdx.x * 128, cb = blockIdx.y * 128;
    float acc[2][8][4];
    #pragma unroll
    for (int mi = 0; mi < 2; mi++)
        #pragma unroll
        for (int nj = 0; nj < 8; nj++)
            #pragma unroll
            for (int c = 0; c < 4; c++) acc[mi][nj][c] = 0.f;

    int arow = t & 127, ahalf = t >> 7;
    int bk = t >> 5, bcq = t & 31;

    for (int k0 = 0; k0 < K; k0 += 32) {
        #pragma unroll
        for (int i = 0; i < 4; i++) {
            int kq = ahalf + 2*i;
            int kc = k0 + kq*4;
            int row = rb + arow;
            float4 v = make_float4(0,0,0,0);
            if (row < NN) {
                const float* src; int col;
                if (kc < splitK) { src = A;  col = kc; }
                else             { src = A2; col = kc - splitK; }
                v = *(const float4*)&src[row*lda + col];
            }
            As[arow*36 + kq*4 + 0] = tf32cvt(v.x);
            As[arow*36 + kq*4 + 1] = tf32cvt(v.y);
            As[arow*36 + kq*4 + 2] = tf32cvt(v.z);
            As[arow*36 + kq*4 + 3] = tf32cvt(v.w);
        }
        #pragma unroll
        for (int i = 0; i < 4; i++) {
            int k = bk + 8*i;
            float4 v = *(const float4*)&W[(k0+k)*HIDN + cb + bcq*4];
            Bs[k*136 + bcq*4 + 0] = tf32cvt(v.x);
            Bs[k*136 + bcq*4 + 1] = tf32cvt(v.y);
            Bs[k*136 + bcq*4 + 2] = tf32cvt(v.z);
            Bs[k*136 + bcq*4 + 3] = tf32cvt(v.w);
        }
        __syncthreads();
        #pragma unroll
        for (int kk = 0; kk < 4; kk++) {
            int kb = kk*8;
            unsigned a[2][4];
            #pragma unroll
            for (int mi = 0; mi < 2; mi++) {
                int r0 = wm*32 + mi*16 + grp;
                a[mi][0] = As[r0*36 + kb + qid];
                a[mi][1] = As[(r0+8)*36 + kb + qid];
                a[mi][2] = As[r0*36 + kb + 4 + qid];
                a[mi][3] = As[(r0+8)*36 + kb + 4 + qid];
            }
            #pragma unroll
            for (int nj = 0; nj < 8; nj++) {
                int col = wn*64 + nj*8 + grp;
                unsigned b0 = Bs[(kb + qid)*136 + col];
                unsigned b1 = Bs[(kb + 4 + qid)*136 + col];
                mma8(acc[0][nj], a[0], b0, b1);
                mma8(acc[1][nj], a[1], b0, b1);
            }
        }
        __syncthreads();
    }
    float slope = ps[0];
    #pragma unroll
    for (int mi = 0; mi < 2; mi++) {
        int row0 = rb + wm*32 + mi*16 + grp;
        #pragma unroll
        for (int nj = 0; nj < 8; nj++) {
            int col = cb + wn*64 + nj*8 + qid*2;
            float2 bq = *(const float2*)&bias[col];
            float v0 = acc[mi][nj][0] + bq.x;
            float v1 = acc[mi][nj][1] + bq.y;
            float v2 = acc[mi][nj][2] + bq.x;
            float v3 = acc[mi][nj][3] + bq.y;
            v0 = (v0 >= 0.f) ? v0 : slope*v0;
            v1 = (v1 >= 0.f) ? v1 : slope*v1;
            v2 = (v2 >= 0.f) ? v2 : slope*v2;
            v3 = (v3 >= 0.f) ? v3 : slope*v3;
            if (row0 < NN)     *(float2*)&out[row0*HIDN + col]     = make_float2(v0, v1);
            if (row0 + 8 < NN) *(float2*)&out[(row0+8)*HIDN + col] = make_float2(v2, v3);
        }
    }
}

#define HPITCH 260
__global__ void __launch_bounds__(256) head_kernel(const float* __restrict__ W3,
                                                   const float* __restrict__ b3,
                                                   float* __restrict__ out) {
    extern __shared__ float hs[];
    float* ls = hs + 64*HPITCH;
    __shared__ float w3s[HIDN*NCLS];
    int t = threadIdx.x;
    for (int idx = t; idx < HIDN*NCLS; idx += 256) w3s[idx] = W3[idx];
    int base = blockIdx.x * 64;
    for (int idx = t; idx < 64*64; idx += 256) {
        int r = idx >> 6, c4 = idx & 63;
        int gi = base + r;
        float4 v = make_float4(0,0,0,0);
        if (gi < NN) v = *(const float4*)&d_h2[gi*HIDN + c4*4];
        *(float4*)&hs[r*HPITCH + c4*4] = v;
    }
    __syncthreads();
    int r = t >> 2, q = t & 3;
    float4 a = *(const float4*)&b3[q*4];
    const float* hrow = hs + r*HPITCH;
    #pragma unroll 8
    for (int k = 0; k < HIDN; k++) {
        float h = hrow[k];
        float4 w = *(const float4*)&w3s[k*16 + q*4];
        a.x = fmaf(h, w.x, a.x); a.y = fmaf(h, w.y, a.y);
        a.z = fmaf(h, w.z, a.z); a.w = fmaf(h, w.w, a.w);
    }
    *(float4*)&ls[r*16 + q*4] = a;
    __syncthreads();
    if (t < 64) {
        int gi = base + t;
        if (gi < NN) {
            float v[16];
            #pragma unroll
            for (int c = 0; c < 16; c++) v[c] = ls[t*16 + c];
            float m = v[0];
            #pragma unroll
            for (int c = 1; c < 16; c++) m = fmaxf(m, v[c]);
            float s = 0.f;
            #pragma unroll
            for (int c = 0; c < 16; c++) s += expf(v[c] - m);
            float lse = m + logf(s);
            float* orow = out + gi*NCLS;
            #pragma unroll
            for (int c = 0; c < 16; c += 4) {
                float4 o4 = make_float4(v[c]-lse, v[c+1]-lse, v[c+2]-lse, v[c+3]-lse);
                *(float4*)&orow[c] = o4;
            }
        }
    }
}

extern "C" void kernel_launch(void* const* d_in, const int* in_sizes, int n_in,
                              void* d_out, int out_size) {
    const float* x     = (const float*)d_in[0];
    const float* xcov  = (const float*)d_in[1];
    const float* adjv  = (const float*)d_in[2];
    const float* fcorr = (const float*)d_in[3];
    const float* gamma = (const float*)d_in[4];
    const float* beta  = (const float*)d_in[5];
    const float* W0    = (const float*)d_in[6];
    const float* C0    = (const float*)d_in[7];
    const float* W1    = (const float*)d_in[8];
    const float* C1    = (const float*)d_in[9];
    const float* mW1   = (const float*)d_in[12];
    const float* mb1   = (const float*)d_in[13];
    const float* mp1   = (const float*)d_in[14];
    const float* mW2   = (const float*)d_in[15];
    const float* mb2   = (const float*)d_in[16];
    const float* mp2   = (const float*)d_in[17];
    const float* mW3   = (const float*)d_in[18];
    const float* mb3   = (const float*)d_in[19];
    const int*   cols  = (const int*)d_in[21];
    float* out = (float*)d_out;

    static int inited = 0;
    const int ASMEM = 82432 + 256;
    const int HSMEM = (64*HPITCH + 64*16) * 4;
    if (!inited) {
        cudaFuncSetAttribute(assign0_kernel, cudaFuncAttributeMaxDynamicSharedMemorySize, ASMEM);
        cudaFuncSetAttribute(head_kernel,    cudaFuncAttributeMaxDynamicSharedMemorySize, HSMEM);
        inited = 1;
    }

    zero_kernel<<<338, 256>>>();
    bn_stats_kernel<<<240, 256>>>(x);
    bn_apply_kernel<<<(NN*FF+255)/256, 256>>>(x, gamma, beta);
    prep_kernel<<<CB1, 256>>>(W0, C0, W1, C1);
    assign0_kernel<<<(NN+127)/128, 256, ASMEM>>>(xcov);
    pool0_accum_kernel<<<(NN*FF+255)/256, 256>>>(xcov);
    assign1_kernel<<<(NP0+127)/128, 128>>>();
    pool1_accum_kernel<<<(NP0*FF+255)/256, 256>>>();
    level1_kernel<<<1, 256>>>(fcorr);
    corr1_kernel<<<(NP0*FF+255)/256, 256>>>();
    loss_kernel<<<1, 256>>>(out);
    prop0_kernel<<<(NN*32+255)/256, 256>>>(adjv, cols);
    prop1_kernel<<<(NN*32+255)/256, 256>>>(cols);
    dim3 ggrid((NN+127)/128, 2);
    gemm_tc_kernel<<<ggrid, 256>>>(0, mW1, mb1, mp1);
    gemm_tc_kernel<<<ggrid, 256>>>(1, mW2, mb2, mp2);
    head_kernel<<<(NN+63)/64, 256, HSMEM>>>(mW3, mb3, out);
}